// round 3
// baseline (speedup 1.0000x reference)
#include <cuda_runtime.h>
#include <cstdint>

#define NN 100000
#define NE 1600000
#define NF 128
#define HD 64

// ---------------- scratch (no allocs allowed) ----------------
__device__ __align__(16) float g_dinv[NN];      // deg -> rsqrt(deg)
__device__ __align__(16) float g_t  [NN * HD];  // (h @ W) * dinv[row]
__device__ __align__(16) float g_acc[NN * HD];  // edge aggregation
__device__ __align__(16) float g_h  [NN * HD];  // layer output
__device__ float g_loss;
__device__ int   g_lsum;

// ---------------- small init kernels ----------------
__global__ void k_zero_small() { g_loss = 0.0f; g_lsum = 0; }

__global__ void k_init(const int* __restrict__ labels) {
    int i = blockIdx.x * blockDim.x + threadIdx.x;
    int v = 0;
    if (i < NN) { g_dinv[i] = 1.0f; v = labels[i]; }
    #pragma unroll
    for (int off = 16; off; off >>= 1) v += __shfl_down_sync(0xffffffffu, v, off);
    if ((threadIdx.x & 31) == 0 && v) atomicAdd(&g_lsum, v);
}

__global__ void k_deg(const int* __restrict__ ei) {
    int e = blockIdx.x * blockDim.x + threadIdx.x;
    if (e < NE) {
        unsigned c = (unsigned)ei[NE + e];   // targets
        if (c < NN) atomicAdd(&g_dinv[c], 1.0f);
    }
}

__global__ void k_rsqrt() {
    int i = blockIdx.x * blockDim.x + threadIdx.x;
    if (i < NN) g_dinv[i] = rsqrtf(g_dinv[i]);
}

// ---------------- GEMM + dinv scale + acc zero ----------------
// t[i,:] = (hin[i,:] @ W) * dinv[i];  acc[i,:] = 0
// block = 256 threads = 4 rows x 64 cols; W cached in smem; grid-stride over rows.
template <int K, bool USEG>
__global__ void k_gemm(const float* __restrict__ hin, const float* __restrict__ W) {
    __shared__ __align__(16) float sW[K * HD];
    __shared__ __align__(16) float srow[4][K];
    const float* src = USEG ? g_h : hin;
    int tid = threadIdx.x;
    for (int j = tid; j < K * HD; j += 256) sW[j] = W[j];
    __syncthreads();

    int r = tid >> 6;       // 0..3
    int c = tid & 63;       // 0..63

    for (int rb = blockIdx.x * 4; rb < NN; rb += gridDim.x * 4) {
        for (int j = tid; j < 4 * K; j += 256)
            srow[j / K][j % K] = src[(size_t)rb * K + j];
        __syncthreads();

        float s = 0.f;
        #pragma unroll
        for (int k = 0; k < K; k += 4) {
            float4 hv = *(const float4*)&srow[r][k];
            s += hv.x * sW[(k + 0) * HD + c];
            s += hv.y * sW[(k + 1) * HD + c];
            s += hv.z * sW[(k + 2) * HD + c];
            s += hv.w * sW[(k + 3) * HD + c];
        }
        int gr = rb + r;
        float sc = s * g_dinv[gr];
        g_t  [(size_t)gr * HD + c] = sc;
        g_acc[(size_t)gr * HD + c] = 0.f;
        __syncthreads();
    }
}

// ---------------- edge scatter: acc[col] += t[row] ----------------
// 16 threads per edge, float4 gather + 4 scalar atomics
__global__ void k_scatter(const int* __restrict__ ei) {
    long long idx = (long long)blockIdx.x * blockDim.x + threadIdx.x;
    int e = (int)(idx >> 4);
    if (e >= NE) return;
    int part = ((int)idx) & 15;
    unsigned rsrc = (unsigned)ei[e];
    unsigned cdst = (unsigned)ei[NE + e];
    if (rsrc >= NN || cdst >= NN) return;
    float4 v = *(const float4*)&g_t[(size_t)rsrc * HD + part * 4];
    float* dst = &g_acc[(size_t)cdst * HD + part * 4];
    atomicAdd(dst + 0, v.x);
    atomicAdd(dst + 1, v.y);
    atomicAdd(dst + 2, v.z);
    atomicAdd(dst + 3, v.w);
}

// ---------------- combine: h = relu(dinv[c]*(acc + t) + b) ----------------
__global__ void k_combine(const float* __restrict__ b) {
    int idx = blockIdx.x * blockDim.x + threadIdx.x;   // float4 units
    if (idx >= NN * HD / 4) return;
    int node = idx >> 4;
    int jc = (idx & 15) * 4;
    float d = g_dinv[node];
    float4 a = ((const float4*)g_acc)[idx];
    float4 t = ((const float4*)g_t)[idx];
    float4 bb = *(const float4*)&b[jc];
    float4 o;
    o.x = fmaxf(fmaf(d, a.x + t.x, bb.x), 0.f);
    o.y = fmaxf(fmaf(d, a.y + t.y, bb.y), 0.f);
    o.z = fmaxf(fmaf(d, a.z + t.z, bb.z), 0.f);
    o.w = fmaxf(fmaf(d, a.w + t.w, bb.w), 0.f);
    ((float4*)g_h)[idx] = o;
}

// ---------------- MLP head + p output + weighted-BCE partial sums ----------------
__global__ void k_head(const float* __restrict__ lW1, const float* __restrict__ lb1,
                       const float* __restrict__ lW2, const float* __restrict__ lb2,
                       const int* __restrict__ labels, float* __restrict__ out_p) {
    __shared__ float sW1[HD * 8];
    __shared__ float sb1[8];
    __shared__ float sW2[8];
    __shared__ float swsum[8];
    int tid = threadIdx.x;
    for (int j = tid; j < HD * 8; j += 256) sW1[j] = lW1[j];
    if (tid < 8) { sb1[tid] = lb1[tid]; sW2[tid] = lW2[tid]; }
    __syncthreads();

    int i = blockIdx.x * 256 + tid;
    float term = 0.f;
    if (i < NN) {
        float z[8];
        #pragma unroll
        for (int o = 0; o < 8; o++) z[o] = sb1[o];
        const float* hr = &g_h[(size_t)i * HD];
        #pragma unroll
        for (int j4 = 0; j4 < HD; j4 += 4) {
            float4 hv = *(const float4*)&hr[j4];
            #pragma unroll
            for (int o = 0; o < 8; o++) {
                z[o] += hv.x * sW1[(j4 + 0) * 8 + o];
                z[o] += hv.y * sW1[(j4 + 1) * 8 + o];
                z[o] += hv.z * sW1[(j4 + 2) * 8 + o];
                z[o] += hv.w * sW1[(j4 + 3) * 8 + o];
            }
        }
        float z2 = lb2[0];
        #pragma unroll
        for (int o = 0; o < 8; o++) z2 += fmaxf(z[o], 0.f) * sW2[o];
        float p = 1.f / (1.f + expf(-z2));
        out_p[i] = p;

        float pm = (float)g_lsum * (1.0f / NN);
        float y = (float)labels[i];
        float w = y * (1.f - pm) + (1.f - y) * pm;
        float pc = fminf(fmaxf(p, 1e-7f), 1.f - 1e-7f);
        float bce = -(y * logf(pc) + (1.f - y) * logf(1.f - pc));
        term = w * bce;
    }
    #pragma unroll
    for (int off = 16; off; off >>= 1) term += __shfl_down_sync(0xffffffffu, term, off);
    if ((tid & 31) == 0) swsum[tid >> 5] = term;
    __syncthreads();
    if (tid == 0) {
        float s = 0.f;
        #pragma unroll
        for (int k2 = 0; k2 < 8; k2++) s += swsum[k2];
        atomicAdd(&g_loss, s);
    }
}

__global__ void k_final(float* __restrict__ out) {
    out[0] = g_loss * (1.0f / NN);
}

// ---------------- launch ----------------
extern "C" void kernel_launch(void* const* d_in, const int* in_sizes, int n_in,
                              void* d_out, int out_size) {
    const float* x      = (const float*)d_in[0];
    const int*   ei     = (const int*)d_in[1];      // int32 (jax x64 disabled)
    const int*   labels = (const int*)d_in[2];
    const float* W1  = (const float*)d_in[3];
    const float* b1  = (const float*)d_in[4];
    const float* W2  = (const float*)d_in[5];
    const float* b2  = (const float*)d_in[6];
    const float* W3  = (const float*)d_in[7];
    const float* b3  = (const float*)d_in[8];
    const float* lW1 = (const float*)d_in[9];
    const float* lb1 = (const float*)d_in[10];
    const float* lW2 = (const float*)d_in[11];
    const float* lb2 = (const float*)d_in[12];

    float* out = (float*)d_out;
    // assume output = [loss, p(100000)]; generalize offset if out_size differs
    int loss_elems = out_size - NN;
    float* out_p = out + (loss_elems > 0 ? loss_elems : 0);

    const int TPB = 256;
    k_zero_small<<<1, 1>>>();
    k_init<<<(NN + TPB - 1) / TPB, TPB>>>(labels);
    k_deg<<<(NE + TPB - 1) / TPB, TPB>>>(ei);
    k_rsqrt<<<(NN + TPB - 1) / TPB, TPB>>>();

    long long scat_threads = (long long)NE * 16;
    int scat_blocks = (int)((scat_threads + TPB - 1) / TPB);
    int comb_blocks = (NN * HD / 4 + TPB - 1) / TPB;

    // layer 1 (K = 128)
    k_gemm<NF, false><<<592, TPB>>>(x, W1);
    k_scatter<<<scat_blocks, TPB>>>(ei);
    k_combine<<<comb_blocks, TPB>>>(b1);

    // layer 2 (K = 64)
    k_gemm<HD, true><<<592, TPB>>>(nullptr, W2);
    k_scatter<<<scat_blocks, TPB>>>(ei);
    k_combine<<<comb_blocks, TPB>>>(b2);

    // layer 3 (K = 64)
    k_gemm<HD, true><<<592, TPB>>>(nullptr, W3);
    k_scatter<<<scat_blocks, TPB>>>(ei);
    k_combine<<<comb_blocks, TPB>>>(b3);

    // head + loss
    k_head<<<(NN + TPB - 1) / TPB, TPB>>>(lW1, lb1, lW2, lb2, labels, out_p);
    if (loss_elems > 0) k_final<<<1, 1>>>(out);
}

// round 4
// speedup vs baseline: 2.5702x; 2.5702x over previous
#include <cuda_runtime.h>
#include <cstdint>

#define NN 100000
#define NE 1600000
#define NF 128
#define HD 64

// ---------------- scratch (no allocs allowed) ----------------
__device__ __align__(16) float g_dinv[NN];
__device__ __align__(16) float g_t  [NN * HD];   // (h @ W) * dinv[row]
__device__ __align__(16) float g_h  [NN * HD];   // layer output
__device__ int g_deg[NN];
__device__ int g_cursor[NN];
__device__ int g_rowstart[NN + 1];
__device__ int g_csr[NE];
__device__ float g_loss;
__device__ int   g_lsum;

// ---------------- init: zero counters, label sum ----------------
__global__ void k_init(const int* __restrict__ labels) {
    int i = blockIdx.x * blockDim.x + threadIdx.x;
    if (i == 0) { g_loss = 0.f; g_lsum = 0; }
    int v = 0;
    if (i < NN) { g_deg[i] = 0; g_cursor[i] = 0; v = labels[i]; }
    #pragma unroll
    for (int off = 16; off; off >>= 1) v += __shfl_down_sync(0xffffffffu, v, off);
    if ((threadIdx.x & 31) == 0 && v) atomicAdd(&g_lsum, v);
}

// grid-stride over edges: histogram destinations
__global__ void k_count(const int* __restrict__ ei) {
    int e = blockIdx.x * blockDim.x + threadIdx.x;
    if (e < NE) {
        unsigned c = (unsigned)ei[NE + e];
        if (c < NN) atomicAdd(&g_deg[c], 1);
    }
}

// one block, 1024 threads: exclusive prefix sum of deg -> rowstart
__global__ void k_scan() {
    const int T = 1024;
    const int CH = (NN + T - 1) / T;   // 98
    __shared__ int sh[T];
    int tid = threadIdx.x;
    int lo = tid * CH, hi = lo + CH; if (hi > NN) hi = NN;
    int s = 0;
    for (int i = lo; i < hi; i++) s += g_deg[i];
    sh[tid] = s;
    __syncthreads();
    // Hillis-Steele inclusive scan
    for (int off = 1; off < T; off <<= 1) {
        int v = (tid >= off) ? sh[tid - off] : 0;
        __syncthreads();
        sh[tid] += v;
        __syncthreads();
    }
    int run = sh[tid] - s;   // exclusive
    for (int i = lo; i < hi; i++) { g_rowstart[i] = run; run += g_deg[i]; }
    if (tid == T - 1) g_rowstart[NN] = run;
}

__global__ void k_dinv() {
    int i = blockIdx.x * blockDim.x + threadIdx.x;
    if (i < NN) g_dinv[i] = rsqrtf((float)(g_deg[i] + 1));  // +1 self loop
}

// fill CSR: for each edge, append src to dst's list
__global__ void k_fill(const int* __restrict__ ei) {
    int e = blockIdx.x * blockDim.x + threadIdx.x;
    if (e >= NE) return;
    unsigned src = (unsigned)ei[e];
    unsigned dst = (unsigned)ei[NE + e];
    if (src >= NN || dst >= NN) return;
    int pos = g_rowstart[dst] + atomicAdd(&g_cursor[dst], 1);
    g_csr[pos] = (int)src;
}

// ---------------- GEMM: t[i,:] = (hin[i,:] @ W) * dinv[i] ----------------
// block 256 = 64 cols x 4 row-threads; 32-row tile; 8 rows/thread register acc.
template <int K, bool USEG>
__global__ void k_gemm(const float* __restrict__ hin, const float* __restrict__ W) {
    __shared__ __align__(16) float sW[K * HD];           // K=128: 32KB, K=64: 16KB
    __shared__ __align__(16) float4 srow[32][K / 4];     // K=128: 16KB, K=64: 8KB
    const float* src = USEG ? g_h : hin;
    int tid = threadIdx.x;
    for (int j = tid; j < K * HD / 4; j += 256)
        ((float4*)sW)[j] = ((const float4*)W)[j];

    int c  = tid & 63;     // column 0..63
    int rt = tid >> 6;     // row-thread 0..3, owns rows rt*8..rt*8+7

    for (int rb = blockIdx.x * 32; rb < NN; rb += gridDim.x * 32) {
        __syncthreads();
        for (int j = tid; j < 32 * (K / 4); j += 256) {
            int r = j / (K / 4), kk = j % (K / 4);
            srow[r][kk] = ((const float4*)(src + (size_t)(rb + r) * K))[kk];
        }
        __syncthreads();

        float acc[8];
        #pragma unroll
        for (int rr = 0; rr < 8; rr++) acc[rr] = 0.f;

        #pragma unroll
        for (int k4 = 0; k4 < K / 4; k4++) {
            float w0 = sW[(4 * k4 + 0) * HD + c];
            float w1 = sW[(4 * k4 + 1) * HD + c];
            float w2 = sW[(4 * k4 + 2) * HD + c];
            float w3 = sW[(4 * k4 + 3) * HD + c];
            #pragma unroll
            for (int rr = 0; rr < 8; rr++) {
                float4 h = srow[rt * 8 + rr][k4];
                acc[rr] = fmaf(h.x, w0, acc[rr]);
                acc[rr] = fmaf(h.y, w1, acc[rr]);
                acc[rr] = fmaf(h.z, w2, acc[rr]);
                acc[rr] = fmaf(h.w, w3, acc[rr]);
            }
        }
        #pragma unroll
        for (int rr = 0; rr < 8; rr++) {
            int gr = rb + rt * 8 + rr;
            g_t[(size_t)gr * HD + c] = acc[rr] * g_dinv[gr];
        }
    }
}

// ---------------- aggregate + combine: h = relu(dinv*(t[self] + sum t[src]) + b)
// 16 threads per node (each owns one float4 of the 64-wide row)
__global__ void k_agg(const float* __restrict__ b) {
    int tid  = threadIdx.x;
    int node = blockIdx.x * 16 + (tid >> 4);
    int part = tid & 15;
    if (node >= NN) return;

    const float4* t4 = (const float4*)g_t;
    int s = g_rowstart[node];
    int e = g_rowstart[node + 1];

    float4 acc = t4[(size_t)node * 16 + part];   // self loop
    int i = s;
    for (; i + 2 <= e; i += 2) {
        int s0 = g_csr[i];
        int s1 = g_csr[i + 1];
        float4 v0 = t4[(size_t)s0 * 16 + part];
        float4 v1 = t4[(size_t)s1 * 16 + part];
        acc.x += v0.x; acc.y += v0.y; acc.z += v0.z; acc.w += v0.w;
        acc.x += v1.x; acc.y += v1.y; acc.z += v1.z; acc.w += v1.w;
    }
    if (i < e) {
        float4 v = t4[(size_t)g_csr[i] * 16 + part];
        acc.x += v.x; acc.y += v.y; acc.z += v.z; acc.w += v.w;
    }

    float d = g_dinv[node];
    float4 bb = *(const float4*)&b[part * 4];
    float4 o;
    o.x = fmaxf(fmaf(d, acc.x, bb.x), 0.f);
    o.y = fmaxf(fmaf(d, acc.y, bb.y), 0.f);
    o.z = fmaxf(fmaf(d, acc.z, bb.z), 0.f);
    o.w = fmaxf(fmaf(d, acc.w, bb.w), 0.f);
    ((float4*)g_h)[(size_t)node * 16 + part] = o;
}

// ---------------- MLP head + p output + weighted-BCE ----------------
__global__ void k_head(const float* __restrict__ lW1, const float* __restrict__ lb1,
                       const float* __restrict__ lW2, const float* __restrict__ lb2,
                       const int* __restrict__ labels, float* __restrict__ out_p) {
    __shared__ float sW1[HD * 8];
    __shared__ float sb1[8];
    __shared__ float sW2[8];
    __shared__ float swsum[8];
    int tid = threadIdx.x;
    for (int j = tid; j < HD * 8; j += 256) sW1[j] = lW1[j];
    if (tid < 8) { sb1[tid] = lb1[tid]; sW2[tid] = lW2[tid]; }
    __syncthreads();

    int i = blockIdx.x * 256 + tid;
    float term = 0.f;
    if (i < NN) {
        float z[8];
        #pragma unroll
        for (int o = 0; o < 8; o++) z[o] = sb1[o];
        const float* hr = &g_h[(size_t)i * HD];
        #pragma unroll
        for (int j4 = 0; j4 < HD; j4 += 4) {
            float4 hv = *(const float4*)&hr[j4];
            #pragma unroll
            for (int o = 0; o < 8; o++) {
                z[o] = fmaf(hv.x, sW1[(j4 + 0) * 8 + o], z[o]);
                z[o] = fmaf(hv.y, sW1[(j4 + 1) * 8 + o], z[o]);
                z[o] = fmaf(hv.z, sW1[(j4 + 2) * 8 + o], z[o]);
                z[o] = fmaf(hv.w, sW1[(j4 + 3) * 8 + o], z[o]);
            }
        }
        float z2 = lb2[0];
        #pragma unroll
        for (int o = 0; o < 8; o++) z2 += fmaxf(z[o], 0.f) * sW2[o];
        float p = 1.f / (1.f + expf(-z2));
        out_p[i] = p;

        float pm = (float)g_lsum * (1.0f / NN);
        float y = (float)labels[i];
        float w = y * (1.f - pm) + (1.f - y) * pm;
        float pc = fminf(fmaxf(p, 1e-7f), 1.f - 1e-7f);
        float bce = -(y * logf(pc) + (1.f - y) * logf(1.f - pc));
        term = w * bce;
    }
    #pragma unroll
    for (int off = 16; off; off >>= 1) term += __shfl_down_sync(0xffffffffu, term, off);
    if ((tid & 31) == 0) swsum[tid >> 5] = term;
    __syncthreads();
    if (tid == 0) {
        float s = 0.f;
        #pragma unroll
        for (int k2 = 0; k2 < 8; k2++) s += swsum[k2];
        atomicAdd(&g_loss, s);
    }
}

__global__ void k_final(float* __restrict__ out) {
    out[0] = g_loss * (1.0f / NN);
}

// ---------------- launch ----------------
extern "C" void kernel_launch(void* const* d_in, const int* in_sizes, int n_in,
                              void* d_out, int out_size) {
    const float* x      = (const float*)d_in[0];
    const int*   ei     = (const int*)d_in[1];
    const int*   labels = (const int*)d_in[2];
    const float* W1  = (const float*)d_in[3];
    const float* b1  = (const float*)d_in[4];
    const float* W2  = (const float*)d_in[5];
    const float* b2  = (const float*)d_in[6];
    const float* W3  = (const float*)d_in[7];
    const float* b3  = (const float*)d_in[8];
    const float* lW1 = (const float*)d_in[9];
    const float* lb1 = (const float*)d_in[10];
    const float* lW2 = (const float*)d_in[11];
    const float* lb2 = (const float*)d_in[12];

    float* out = (float*)d_out;
    int loss_elems = out_size - NN;
    float* out_p = out + (loss_elems > 0 ? loss_elems : 0);

    const int TPB = 256;
    const int NB_N = (NN + TPB - 1) / TPB;
    const int NB_E = (NE + TPB - 1) / TPB;

    // CSR build (per-launch, deterministic input -> same structure)
    k_init <<<NB_N, TPB>>>(labels);
    k_count<<<NB_E, TPB>>>(ei);
    k_scan <<<1, 1024>>>();
    k_dinv <<<NB_N, TPB>>>();
    k_fill <<<NB_E, TPB>>>(ei);

    const int agg_blocks = (NN + 15) / 16;

    // layer 1 (K = 128)
    k_gemm<NF, false><<<592, TPB>>>(x, W1);
    k_agg<<<agg_blocks, TPB>>>(b1);
    // layer 2 (K = 64)
    k_gemm<HD, true><<<592, TPB>>>(nullptr, W2);
    k_agg<<<agg_blocks, TPB>>>(b2);
    // layer 3 (K = 64)
    k_gemm<HD, true><<<592, TPB>>>(nullptr, W3);
    k_agg<<<agg_blocks, TPB>>>(b3);

    // head + loss
    k_head<<<NB_N, TPB>>>(lW1, lb1, lW2, lb2, labels, out_p);
    if (loss_elems > 0) k_final<<<1, 1>>>(out);
}